// round 1
// baseline (speedup 1.0000x reference)
#include <cuda_runtime.h>
#include <cuda_bf16.h>
#include <limits.h>

#define B_DIM 32
#define C_DIM 8
#define H_DIM 512
#define W_DIM 512
#define N_IMG (B_DIM * C_DIM)          // 256
#define IMG_ELEMS (H_DIM * W_DIM)      // 262144
#define IMG_F4 (IMG_ELEMS / 4)         // 65536 float4 per image
#define CHUNKS 8                        // blocks per image
#define THREADS 256
#define F4_PER_THREAD (IMG_F4 / (CHUNKS * THREADS))  // 32

// Scratch: per-image running min/max (int coords). Re-initialized each launch
// by the init kernel (graph replays require deterministic reset).
__device__ int g_xmin[N_IMG];
__device__ int g_xmax[N_IMG];
__device__ int g_ymin[N_IMG];
__device__ int g_ymax[N_IMG];

__global__ void bb_init_kernel() {
    int i = threadIdx.x;  // 256 threads, one per image
    g_xmin[i] = INT_MAX;
    g_ymin[i] = INT_MAX;
    g_xmax[i] = 0;
    g_ymax[i] = 0;
}

__global__ __launch_bounds__(THREADS) void bb_reduce_kernel(const float* __restrict__ mask) {
    const int img   = blockIdx.y;              // 0..255
    const int chunk = blockIdx.x;              // 0..7
    const int tid   = threadIdx.x;

    const float4* __restrict__ img_f4 =
        reinterpret_cast<const float4*>(mask) + (size_t)img * IMG_F4;

    int xmin = INT_MAX, ymin = INT_MAX;
    int xmax = 0,       ymax = 0;

    // Coalesced: thread t reads f4 index chunk*8192 + k*256 + t
    const int base = chunk * (THREADS * F4_PER_THREAD);

#pragma unroll 8
    for (int k = 0; k < F4_PER_THREAD; k++) {
        const int idx = base + k * THREADS + tid;   // float4 index within image
        const float4 v = img_f4[idx];

        const int h1 = (idx >> 7) + 1;              // row + 1 (128 f4 per row)
        const int w0 = ((idx & 127) << 2) + 1;      // first col + 1

        // lane 0
        {
            const bool a = v.x >= 0.5f;
            const int xv = a ? (w0 + 0) : 0;
            const int yv = a ? h1 : 0;
            xmin = min(xmin, xv); xmax = max(xmax, xv);
            ymin = min(ymin, yv); ymax = max(ymax, yv);
        }
        {
            const bool a = v.y >= 0.5f;
            const int xv = a ? (w0 + 1) : 0;
            const int yv = a ? h1 : 0;
            xmin = min(xmin, xv); xmax = max(xmax, xv);
            ymin = min(ymin, yv); ymax = max(ymax, yv);
        }
        {
            const bool a = v.z >= 0.5f;
            const int xv = a ? (w0 + 2) : 0;
            const int yv = a ? h1 : 0;
            xmin = min(xmin, xv); xmax = max(xmax, xv);
            ymin = min(ymin, yv); ymax = max(ymax, yv);
        }
        {
            const bool a = v.w >= 0.5f;
            const int xv = a ? (w0 + 3) : 0;
            const int yv = a ? h1 : 0;
            xmin = min(xmin, xv); xmax = max(xmax, xv);
            ymin = min(ymin, yv); ymax = max(ymax, yv);
        }
    }

    // Warp reduce (redux.sync, sm_80+)
    xmin = __reduce_min_sync(0xFFFFFFFFu, xmin);
    xmax = __reduce_max_sync(0xFFFFFFFFu, xmax);
    ymin = __reduce_min_sync(0xFFFFFFFFu, ymin);
    ymax = __reduce_max_sync(0xFFFFFFFFu, ymax);

    __shared__ int s_xmin[8], s_xmax[8], s_ymin[8], s_ymax[8];
    const int wid = tid >> 5;
    const int lid = tid & 31;
    if (lid == 0) {
        s_xmin[wid] = xmin; s_xmax[wid] = xmax;
        s_ymin[wid] = ymin; s_ymax[wid] = ymax;
    }
    __syncthreads();

    if (wid == 0) {
        int bxmin = s_xmin[lid & 7], bxmax = s_xmax[lid & 7];
        int bymin = s_ymin[lid & 7], bymax = s_ymax[lid & 7];
        bxmin = __reduce_min_sync(0xFFFFFFFFu, bxmin);
        bxmax = __reduce_max_sync(0xFFFFFFFFu, bxmax);
        bymin = __reduce_min_sync(0xFFFFFFFFu, bymin);
        bymax = __reduce_max_sync(0xFFFFFFFFu, bymax);
        if (lid == 0) {
            atomicMin(&g_xmin[img], bxmin);
            atomicMax(&g_xmax[img], bxmax);
            atomicMin(&g_ymin[img], bymin);
            atomicMax(&g_ymax[img], bymax);
        }
    }
}

// Output layout (concatenated flattened tuple, all float32):
//   [0,   256)  object_found            [B, C, 1]
//   [256, 1280) bounding_boxes_scaled   [B, C, 4]  (x_min, y_min, x_max, y_max)
//   [1280,2304) bounding_boxes          [B, C, 4]  (scaled * 2)
__global__ void bb_final_kernel(float* __restrict__ out) {
    const int i = threadIdx.x;  // 256 threads, one per (b, c)
    const float xmin = (float)g_xmin[i];
    const float xmax = (float)g_xmax[i];
    const float ymin = (float)g_ymin[i];
    const float ymax = (float)g_ymax[i];

    const float found = ((ymax > ymin) && (xmax > xmin)) ? 1.0f : 0.0f;

    out[i] = found;

    float* bb = out + 256 + i * 4;
    bb[0] = xmin; bb[1] = ymin; bb[2] = xmax; bb[3] = ymax;

    float* bb2 = out + 1280 + i * 4;
    bb2[0] = xmin * 2.0f; bb2[1] = ymin * 2.0f;
    bb2[2] = xmax * 2.0f; bb2[3] = ymax * 2.0f;
}

extern "C" void kernel_launch(void* const* d_in, const int* in_sizes, int n_in,
                              void* d_out, int out_size) {
    const float* mask = (const float*)d_in[0];
    float* out = (float*)d_out;

    bb_init_kernel<<<1, N_IMG>>>();
    dim3 grid(CHUNKS, N_IMG);
    bb_reduce_kernel<<<grid, THREADS>>>(mask);
    bb_final_kernel<<<1, N_IMG>>>(out);
}